// round 2
// baseline (speedup 1.0000x reference)
#include <cuda_runtime.h>

// Problem constants (fixed shapes from the reference)
#define H     40
#define KPTS  15
#define CIN   128
#define COUT  128
#define NMAX  20000
#define KDIM  (KPTS * CIN)   // 1920
#define KP_EXTENT_INV (1.0f / 1.2f)

// Scratch: weighted[n][k][c], fp32. 20000*15*128*4 = 153.6 MB static device array.
__device__ float g_weighted[(size_t)NMAX * KPTS * CIN];

// ---------------------------------------------------------------------------
// Kernel 1: per-query influence weighting + neighbor feature aggregation.
// One CTA per query point n, 128 threads (thread t owns feature channel c=t).
// ---------------------------------------------------------------------------
__global__ void __launch_bounds__(CIN) kp_weight_kernel(
    const float* __restrict__ q_pts,    // [N,3]
    const float* __restrict__ s_pts,    // [Ns,3]
    const int*   __restrict__ nb,       // [N,H]
    const float* __restrict__ x,        // [Ns,CIN]
    const float* __restrict__ kp,       // [KPTS,3]
    int N, int Ns)
{
    int n = blockIdx.x;
    int t = threadIdx.x;

    __shared__ float s_kp[KPTS * 3];
    __shared__ int   s_idx[H];
    __shared__ float s_w[KPTS][H];
    __shared__ float s_feat[H][CIN];

    if (t < KPTS * 3) s_kp[t] = kp[t];
    __syncthreads();

    // Threads 0..H-1: gather neighbor coords, compute influence weights.
    if (t < H) {
        int idx = nb[(size_t)n * H + t];
        bool valid = ((unsigned)idx < (unsigned)Ns);
        s_idx[t] = valid ? idx : -1;
        float px = 0.f, py = 0.f, pz = 0.f;
        if (valid) {
            float qx = q_pts[n * 3 + 0];
            float qy = q_pts[n * 3 + 1];
            float qz = q_pts[n * 3 + 2];
            px = s_pts[(size_t)idx * 3 + 0] - qx;
            py = s_pts[(size_t)idx * 3 + 1] - qy;
            pz = s_pts[(size_t)idx * 3 + 2] - qz;
        }
        #pragma unroll
        for (int k = 0; k < KPTS; k++) {
            float dx = px - s_kp[k * 3 + 0];
            float dy = py - s_kp[k * 3 + 1];
            float dz = pz - s_kp[k * 3 + 2];
            float d2 = dx * dx + dy * dy + dz * dz;
            float w  = fmaxf(1.0f - sqrtf(d2) * KP_EXTENT_INV, 0.0f);
            s_w[k][t] = valid ? w : 0.0f;
        }
    }
    __syncthreads();

    // Gather neighbor feature rows into smem (coalesced: 128 threads x 4B per row).
    #pragma unroll 4
    for (int h = 0; h < H; h++) {
        int idx = s_idx[h];
        s_feat[h][t] = (idx >= 0) ? x[(size_t)idx * CIN + t] : 0.0f;
    }
    __syncthreads();

    // weighted[k][c=t] = sum_h w[k][h] * feat[h][t]. Each feature value read once,
    // broadcast w from smem, 15 accumulators in registers.
    float acc[KPTS];
    #pragma unroll
    for (int k = 0; k < KPTS; k++) acc[k] = 0.0f;

    #pragma unroll
    for (int h = 0; h < H; h++) {
        float f = s_feat[h][t];
        #pragma unroll
        for (int k = 0; k < KPTS; k++)
            acc[k] = fmaf(s_w[k][h], f, acc[k]);
    }

    #pragma unroll
    for (int k = 0; k < KPTS; k++)
        g_weighted[((size_t)n * KPTS + k) * CIN + t] = acc[k];
}

// ---------------------------------------------------------------------------
// Kernel 2: GEMM  C[N,128] = A[N,1920] * B[1920,128]
// A = g_weighted (row-major), B = weights (k,c flattened row-major). fp32 SIMT.
// 64x128 CTA tile, BK=16, 256 threads, 4x8 register tile per thread.
// ---------------------------------------------------------------------------
#define BM 64
#define BN 128
#define BK 16

__global__ void __launch_bounds__(256) kp_gemm_kernel(
    const float* __restrict__ B,   // [KDIM, BN] = weights
    float*       __restrict__ C,   // [N, BN]
    int N)
{
    __shared__ float As[BK][BM];
    __shared__ float Bs[BK][BN];

    const float* A = g_weighted;

    int t  = threadIdx.x;           // 0..255
    int m0 = blockIdx.x * BM;

    int ty = t / 16;                // 0..15 : row group (4 rows each)
    int tx = t % 16;                // 0..15 : col group (8 cols each)

    // A tile load mapping: 64 rows x 16 k, one float4 per thread along k.
    int a_row  = t / 4;             // 0..63
    int a_col4 = (t % 4) * 4;       // 0,4,8,12

    // B tile load mapping: 16 k x 128 n, two float4 per thread.
    int b_row  = t / 32;            // 0..7 (and +8)
    int b_col4 = (t % 32) * 4;      // 0..124

    float cacc[4][8];
    #pragma unroll
    for (int i = 0; i < 4; i++)
        #pragma unroll
        for (int j = 0; j < 8; j++) cacc[i][j] = 0.0f;

    for (int k0 = 0; k0 < KDIM; k0 += BK) {
        // Load A tile (transpose into smem so compute reads are contiguous in m).
        {
            int gm = m0 + a_row;
            float4 v = make_float4(0.f, 0.f, 0.f, 0.f);
            if (gm < N)
                v = *(const float4*)&A[(size_t)gm * KDIM + k0 + a_col4];
            As[a_col4 + 0][a_row] = v.x;
            As[a_col4 + 1][a_row] = v.y;
            As[a_col4 + 2][a_row] = v.z;
            As[a_col4 + 3][a_row] = v.w;
        }
        // Load B tile (row-major, directly coalesced).
        {
            float4 v0 = *(const float4*)&B[(size_t)(k0 + b_row) * BN + b_col4];
            float4 v1 = *(const float4*)&B[(size_t)(k0 + b_row + 8) * BN + b_col4];
            *(float4*)&Bs[b_row][b_col4]     = v0;
            *(float4*)&Bs[b_row + 8][b_col4] = v1;
        }
        __syncthreads();

        #pragma unroll
        for (int kk = 0; kk < BK; kk++) {
            float a[4], b[8];
            *(float4*)a       = *(const float4*)&As[kk][ty * 4];
            *(float4*)b       = *(const float4*)&Bs[kk][tx * 8];
            *(float4*)(b + 4) = *(const float4*)&Bs[kk][tx * 8 + 4];
            #pragma unroll
            for (int i = 0; i < 4; i++)
                #pragma unroll
                for (int j = 0; j < 8; j++)
                    cacc[i][j] = fmaf(a[i], b[j], cacc[i][j]);
        }
        __syncthreads();
    }

    // Store 4x8 tile per thread.
    #pragma unroll
    for (int i = 0; i < 4; i++) {
        int gm = m0 + ty * 4 + i;
        if (gm < N) {
            *(float4*)&C[(size_t)gm * BN + tx * 8 + 0] = *(float4*)&cacc[i][0];
            *(float4*)&C[(size_t)gm * BN + tx * 8 + 4] = *(float4*)&cacc[i][4];
        }
    }
}

// ---------------------------------------------------------------------------
// kernel_launch
// Inputs (metadata order): q_pts [N,3] f32, s_pts [Ns,3] f32,
// neighb_inds [N,H] i32, x [Ns,CIN] f32, kernel_points [KPTS,3] f32,
// weights [KPTS,CIN,COUT] f32. Output: [N,COUT] f32.
// ---------------------------------------------------------------------------
extern "C" void kernel_launch(void* const* d_in, const int* in_sizes, int n_in,
                              void* d_out, int out_size)
{
    const float* q_pts = (const float*)d_in[0];
    const float* s_pts = (const float*)d_in[1];
    const int*   nb    = (const int*)d_in[2];
    const float* x     = (const float*)d_in[3];
    const float* kp    = (const float*)d_in[4];
    const float* w     = (const float*)d_in[5];
    float*       out   = (float*)d_out;

    int N  = in_sizes[0] / 3;
    int Ns = in_sizes[1] / 3;

    kp_weight_kernel<<<N, CIN>>>(q_pts, s_pts, nb, x, kp, N, Ns);

    int gridB = (N + BM - 1) / BM;
    kp_gemm_kernel<<<gridB, 256>>>(w, out, N);
}

// round 3
// speedup vs baseline: 2.0124x; 2.0124x over previous
#include <cuda_runtime.h>

// Problem constants (fixed shapes from the reference)
#define H     40
#define KPTS  15
#define CIN   128
#define COUT  128
#define NMAX  20000
#define KDIM  (KPTS * CIN)   // 1920
#define KP_EXTENT_INV (1.0f / 1.2f)

// Scratch: weighted[n][k][c], fp32. 20000*15*128*4 = 153.6 MB static device array.
__device__ float g_weighted[(size_t)NMAX * KPTS * CIN];

// ---------------------------------------------------------------------------
// Kernel 1: influence weighting + neighbor aggregation. Warp-per-query.
// 256 threads = 8 warps = 8 queries per CTA. Lane l owns channels [4l, 4l+3].
// No __syncthreads in hot path: each warp works on its own smem slice.
// ---------------------------------------------------------------------------
__global__ void __launch_bounds__(256) kp_weight_kernel(
    const float* __restrict__ q_pts,    // [N,3]
    const float* __restrict__ s_pts,    // [Ns,3]
    const int*   __restrict__ nb,       // [N,H]
    const float* __restrict__ x,        // [Ns,CIN]
    const float* __restrict__ kp,       // [KPTS,3]
    int N, int Ns)
{
    int wid  = threadIdx.x >> 5;
    int lane = threadIdx.x & 31;
    int n    = blockIdx.x * 8 + wid;

    __shared__ float s_kp[48];              // 15*3 padded
    __shared__ float s_w[8][H][16];         // per-warp weights, [h][k] (k padded to 16)
    __shared__ int   s_idx[8][H];

    if (threadIdx.x < KPTS * 3) s_kp[threadIdx.x] = kp[threadIdx.x];
    __syncthreads();

    if (n < N) {
        float qx = q_pts[n * 3 + 0];
        float qy = q_pts[n * 3 + 1];
        float qz = q_pts[n * 3 + 2];

        // Phase 1: lanes cover h = lane, lane+32. Compute 15 influence weights each.
        for (int h = lane; h < H; h += 32) {
            int idx = nb[(size_t)n * H + h];
            bool valid = ((unsigned)idx < (unsigned)Ns);
            int safe = valid ? idx : 0;
            s_idx[wid][h] = safe;
            float px = s_pts[(size_t)safe * 3 + 0] - qx;
            float py = s_pts[(size_t)safe * 3 + 1] - qy;
            float pz = s_pts[(size_t)safe * 3 + 2] - qz;
            #pragma unroll
            for (int k = 0; k < KPTS; k++) {
                float dx = px - s_kp[k * 3 + 0];
                float dy = py - s_kp[k * 3 + 1];
                float dz = pz - s_kp[k * 3 + 2];
                float d2 = dx * dx + dy * dy + dz * dz;
                float w  = fmaxf(1.0f - sqrtf(d2) * KP_EXTENT_INV, 0.0f);
                s_w[wid][h][k] = valid ? w : 0.0f;
            }
            s_w[wid][h][15] = 0.0f;
        }
        __syncwarp();

        // Phase 2: accumulate acc[k] (float4 over 4 channels) over 40 neighbors.
        float4 acc[KPTS];
        #pragma unroll
        for (int k = 0; k < KPTS; k++) acc[k] = make_float4(0.f, 0.f, 0.f, 0.f);

        const float* xbase = x + (lane << 2);

        #pragma unroll 4
        for (int h = 0; h < H; h++) {
            int idx = s_idx[wid][h];
            float4 f = *(const float4*)(xbase + (size_t)idx * CIN);
            float wk[16];
            const float4* wv = (const float4*)s_w[wid][h];
            *(float4*)&wk[0]  = wv[0];
            *(float4*)&wk[4]  = wv[1];
            *(float4*)&wk[8]  = wv[2];
            *(float4*)&wk[12] = wv[3];
            #pragma unroll
            for (int k = 0; k < KPTS; k++) {
                acc[k].x = fmaf(wk[k], f.x, acc[k].x);
                acc[k].y = fmaf(wk[k], f.y, acc[k].y);
                acc[k].z = fmaf(wk[k], f.z, acc[k].z);
                acc[k].w = fmaf(wk[k], f.w, acc[k].w);
            }
        }

        // Store: weighted[n][k][c]
        float* outp = g_weighted + (size_t)n * KDIM + (lane << 2);
        #pragma unroll
        for (int k = 0; k < KPTS; k++)
            *(float4*)(outp + k * CIN) = acc[k];
    }
}

// ---------------------------------------------------------------------------
// Kernel 2: GEMM  C[N,128] = A[N,1920] * B[1920,128]
// BM=32, BN=128, BK=16, 128 threads, 4x8 reg tile, double-buffered smem with
// register prefetch: ONE __syncthreads per K-iteration. Grid = 625 CTAs.
// ---------------------------------------------------------------------------
#define BM 32
#define BN 128
#define BK 16
#define KITERS (KDIM / BK)   // 120

__global__ void __launch_bounds__(128) kp_gemm_kernel(
    const float* __restrict__ B,   // [KDIM, BN] = weights
    float*       __restrict__ C,   // [N, BN]
    int N)
{
    __shared__ float As[2][BK][BM];   // 4 KB
    __shared__ float Bs[2][BK][BN];   // 16 KB

    const float* A = g_weighted;
    int t  = threadIdx.x;
    int m0 = blockIdx.x * BM;

    // Load maps
    int ar = t >> 2;            // 0..31  A row
    int ac = (t & 3) << 2;      // 0,4,8,12  A k-offset (float4)
    int br = t >> 5;            // 0..3   B k-row (plus +4,+8,+12)
    int bc = (t & 31) << 2;     // 0..124 B col (float4)

    // Compute map: 4x8 per thread
    int ty = t >> 4;            // 0..7
    int tx = t & 15;            // 0..15

    const float* Aptr = A + (size_t)(m0 + ar) * KDIM + ac;
    const float* Bptr = B + (size_t)br * BN + bc;

    // Prologue: load tile 0 into regs, stage into buffer 0.
    float4 a_reg  = *(const float4*)(Aptr);
    float4 b_reg0 = *(const float4*)(Bptr + 0 * 4 * BN);
    float4 b_reg1 = *(const float4*)(Bptr + 1 * 4 * BN);
    float4 b_reg2 = *(const float4*)(Bptr + 2 * 4 * BN);
    float4 b_reg3 = *(const float4*)(Bptr + 3 * 4 * BN);

    As[0][ac + 0][ar] = a_reg.x;
    As[0][ac + 1][ar] = a_reg.y;
    As[0][ac + 2][ar] = a_reg.z;
    As[0][ac + 3][ar] = a_reg.w;
    *(float4*)&Bs[0][br + 0][bc]  = b_reg0;
    *(float4*)&Bs[0][br + 4][bc]  = b_reg1;
    *(float4*)&Bs[0][br + 8][bc]  = b_reg2;
    *(float4*)&Bs[0][br + 12][bc] = b_reg3;
    __syncthreads();

    float acc[4][8];
    #pragma unroll
    for (int i = 0; i < 4; i++)
        #pragma unroll
        for (int j = 0; j < 8; j++) acc[i][j] = 0.0f;

    for (int it = 0; it < KITERS; ++it) {
        int cur = it & 1;

        // Prefetch next tile into registers (overlaps with compute below).
        if (it + 1 < KITERS) {
            const float* Ap = Aptr + (it + 1) * BK;
            a_reg  = *(const float4*)(Ap);
            const float* Bp = Bptr + (size_t)(it + 1) * BK * BN;
            b_reg0 = *(const float4*)(Bp + 0 * 4 * BN);
            b_reg1 = *(const float4*)(Bp + 1 * 4 * BN);
            b_reg2 = *(const float4*)(Bp + 2 * 4 * BN);
            b_reg3 = *(const float4*)(Bp + 3 * 4 * BN);
        }

        // Compute on current buffer.
        #pragma unroll
        for (int kk = 0; kk < BK; kk++) {
            float a[4], b[8];
            *(float4*)a       = *(const float4*)&As[cur][kk][ty * 4];
            *(float4*)b       = *(const float4*)&Bs[cur][kk][tx * 8];
            *(float4*)(b + 4) = *(const float4*)&Bs[cur][kk][tx * 8 + 4];
            #pragma unroll
            for (int i = 0; i < 4; i++)
                #pragma unroll
                for (int j = 0; j < 8; j++)
                    acc[i][j] = fmaf(a[i], b[j], acc[i][j]);
        }

        // Stage next tile into the other buffer (safe: nobody reads it now).
        if (it + 1 < KITERS) {
            int nxt = cur ^ 1;
            As[nxt][ac + 0][ar] = a_reg.x;
            As[nxt][ac + 1][ar] = a_reg.y;
            As[nxt][ac + 2][ar] = a_reg.z;
            As[nxt][ac + 3][ar] = a_reg.w;
            *(float4*)&Bs[nxt][br + 0][bc]  = b_reg0;
            *(float4*)&Bs[nxt][br + 4][bc]  = b_reg1;
            *(float4*)&Bs[nxt][br + 8][bc]  = b_reg2;
            *(float4*)&Bs[nxt][br + 12][bc] = b_reg3;
            __syncthreads();
        }
    }

    // Epilogue: store 4x8 per thread.
    float* Cp = C + (size_t)(m0 + ty * 4) * BN + tx * 8;
    #pragma unroll
    for (int i = 0; i < 4; i++) {
        int gm = m0 + ty * 4 + i;
        if (gm < N) {
            *(float4*)(Cp + (size_t)i * BN + 0) = *(float4*)&acc[i][0];
            *(float4*)(Cp + (size_t)i * BN + 4) = *(float4*)&acc[i][4];
        }
    }
}

// ---------------------------------------------------------------------------
// kernel_launch
// Inputs: q_pts [N,3] f32, s_pts [Ns,3] f32, neighb_inds [N,H] i32,
// x [Ns,CIN] f32, kernel_points [KPTS,3] f32, weights [KPTS,CIN,COUT] f32.
// Output: [N,COUT] f32.
// ---------------------------------------------------------------------------
extern "C" void kernel_launch(void* const* d_in, const int* in_sizes, int n_in,
                              void* d_out, int out_size)
{
    const float* q_pts = (const float*)d_in[0];
    const float* s_pts = (const float*)d_in[1];
    const int*   nb    = (const int*)d_in[2];
    const float* x     = (const float*)d_in[3];
    const float* kp    = (const float*)d_in[4];
    const float* w     = (const float*)d_in[5];
    float*       out   = (float*)d_out;

    int N  = in_sizes[0] / 3;
    int Ns = in_sizes[1] / 3;

    int grid1 = (N + 7) / 8;
    kp_weight_kernel<<<grid1, 256>>>(q_pts, s_pts, nb, x, kp, N, Ns);

    int grid2 = (N + BM - 1) / BM;
    kp_gemm_kernel<<<grid2, 128>>>(w, out, N);
}

// round 7
// speedup vs baseline: 4.7326x; 2.3517x over previous
#include <cuda_runtime.h>
#include <cuda_bf16.h>
#include <cstdint>

// Problem constants (fixed shapes from the reference)
#define H     40
#define KPTS  15
#define CIN   128
#define COUT  128
#define NMAX  20000
#define KDIM  (KPTS * CIN)   // 1920
#define KP_EXTENT_INV (1.0f / 1.2f)

// ---------------------------------------------------------------------------
// Static scratch: split-bf16 operands.
// A = weighted [N, 1920] as hi+lo bf16; B = weights^T [128, 1920] as hi+lo.
// ---------------------------------------------------------------------------
__device__ __nv_bfloat16 g_Ahi[(size_t)NMAX * KDIM];
__device__ __nv_bfloat16 g_Alo[(size_t)NMAX * KDIM];
__device__ __nv_bfloat16 g_Bhi[(size_t)COUT * KDIM];
__device__ __nv_bfloat16 g_Blo[(size_t)COUT * KDIM];

// ---------------------------------------------------------------------------
// PTX helpers (all baseline sm_80+ instructions — safe for compute_103)
// ---------------------------------------------------------------------------
__device__ __forceinline__ uint32_t smem_u32(const void* p) {
    uint32_t a;
    asm("{ .reg .u64 t; cvta.to.shared.u64 t, %1; cvt.u32.u64 %0, t; }" : "=r"(a) : "l"(p));
    return a;
}
__device__ __forceinline__ void cp_async16(uint32_t dst, const void* src) {
    asm volatile("cp.async.cg.shared.global [%0], [%1], 16;\n" :: "r"(dst), "l"(src) : "memory");
}
__device__ __forceinline__ void cp_async_commit() {
    asm volatile("cp.async.commit_group;" ::: "memory");
}
template <int NN>
__device__ __forceinline__ void cp_async_wait() {
    asm volatile("cp.async.wait_group %0;" :: "n"(NN) : "memory");
}
__device__ __forceinline__ void ldm_x4(uint32_t& r0, uint32_t& r1, uint32_t& r2, uint32_t& r3,
                                       uint32_t addr) {
    asm volatile("ldmatrix.sync.aligned.m8n8.x4.shared.b16 {%0,%1,%2,%3}, [%4];"
                 : "=r"(r0), "=r"(r1), "=r"(r2), "=r"(r3) : "r"(addr));
}
__device__ __forceinline__ void mma_bf16(float& c0, float& c1, float& c2, float& c3,
                                         uint32_t a0, uint32_t a1, uint32_t a2, uint32_t a3,
                                         uint32_t b0, uint32_t b1) {
    asm volatile("mma.sync.aligned.m16n8k16.row.col.f32.bf16.bf16.f32 "
                 "{%0,%1,%2,%3}, {%4,%5,%6,%7}, {%8,%9}, {%0,%1,%2,%3};"
                 : "+f"(c0), "+f"(c1), "+f"(c2), "+f"(c3)
                 : "r"(a0), "r"(a1), "r"(a2), "r"(a3), "r"(b0), "r"(b1));
}

__device__ __forceinline__ void split_bf16(float v, __nv_bfloat16& hi, __nv_bfloat16& lo) {
    hi = __float2bfloat16_rn(v);
    lo = __float2bfloat16_rn(v - __bfloat162float(hi));
}

// SW128 swizzled byte offset for (row r [128B rows], 16B segment seg)
__device__ __forceinline__ uint32_t swz(int r, int seg) {
    return (uint32_t)(r * 128 + ((seg * 16) ^ ((r & 7) * 16)));
}

// ---------------------------------------------------------------------------
// Kernel 0: split weights into transposed hi/lo bf16:  Bt[n][k] = W[k][n]
// ---------------------------------------------------------------------------
__global__ void __launch_bounds__(COUT) kp_bprep_kernel(const float* __restrict__ W)
{
    int k = blockIdx.x;
    int n = threadIdx.x;
    float v = W[(size_t)k * COUT + n];
    __nv_bfloat16 hi, lo;
    split_bf16(v, hi, lo);
    g_Bhi[(size_t)n * KDIM + k] = hi;
    g_Blo[(size_t)n * KDIM + k] = lo;
}

// ---------------------------------------------------------------------------
// Kernel 1: influence weighting + neighbor aggregation. Warp-per-query,
// outputs split-bf16 hi/lo rows of the "weighted" matrix.
// ---------------------------------------------------------------------------
__global__ void __launch_bounds__(256) kp_weight_kernel(
    const float* __restrict__ q_pts,    // [N,3]
    const float* __restrict__ s_pts,    // [Ns,3]
    const int*   __restrict__ nb,       // [N,H]
    const float* __restrict__ x,        // [Ns,CIN]
    const float* __restrict__ kp,       // [KPTS,3]
    int N, int Ns)
{
    int wid  = threadIdx.x >> 5;
    int lane = threadIdx.x & 31;
    int n    = blockIdx.x * 8 + wid;

    __shared__ float s_kp[48];
    __shared__ float s_w[8][H][16];
    __shared__ int   s_idx[8][H];

    if (threadIdx.x < KPTS * 3) s_kp[threadIdx.x] = kp[threadIdx.x];
    __syncthreads();

    if (n < N) {
        float qx = q_pts[n * 3 + 0];
        float qy = q_pts[n * 3 + 1];
        float qz = q_pts[n * 3 + 2];

        for (int h = lane; h < H; h += 32) {
            int idx = nb[(size_t)n * H + h];
            bool valid = ((unsigned)idx < (unsigned)Ns);
            int safe = valid ? idx : 0;
            s_idx[wid][h] = safe;
            float px = s_pts[(size_t)safe * 3 + 0] - qx;
            float py = s_pts[(size_t)safe * 3 + 1] - qy;
            float pz = s_pts[(size_t)safe * 3 + 2] - qz;
            #pragma unroll
            for (int k = 0; k < KPTS; k++) {
                float dx = px - s_kp[k * 3 + 0];
                float dy = py - s_kp[k * 3 + 1];
                float dz = pz - s_kp[k * 3 + 2];
                float d2 = dx * dx + dy * dy + dz * dz;
                float w  = fmaxf(1.0f - sqrtf(d2) * KP_EXTENT_INV, 0.0f);
                s_w[wid][h][k] = valid ? w : 0.0f;
            }
            s_w[wid][h][15] = 0.0f;
        }
        __syncwarp();

        float4 acc[KPTS];
        #pragma unroll
        for (int k = 0; k < KPTS; k++) acc[k] = make_float4(0.f, 0.f, 0.f, 0.f);

        const float* xbase = x + (lane << 2);

        #pragma unroll 4
        for (int h = 0; h < H; h++) {
            int idx = s_idx[wid][h];
            float4 f = *(const float4*)(xbase + (size_t)idx * CIN);
            float wk[16];
            const float4* wv = (const float4*)s_w[wid][h];
            *(float4*)&wk[0]  = wv[0];
            *(float4*)&wk[4]  = wv[1];
            *(float4*)&wk[8]  = wv[2];
            *(float4*)&wk[12] = wv[3];
            #pragma unroll
            for (int k = 0; k < KPTS; k++) {
                acc[k].x = fmaf(wk[k], f.x, acc[k].x);
                acc[k].y = fmaf(wk[k], f.y, acc[k].y);
                acc[k].z = fmaf(wk[k], f.z, acc[k].z);
                acc[k].w = fmaf(wk[k], f.w, acc[k].w);
            }
        }

        size_t rowoff = (size_t)n * KDIM + (lane << 2);
        #pragma unroll
        for (int k = 0; k < KPTS; k++) {
            __nv_bfloat16 h0, h1, h2, h3, l0, l1, l2, l3;
            split_bf16(acc[k].x, h0, l0);
            split_bf16(acc[k].y, h1, l1);
            split_bf16(acc[k].z, h2, l2);
            split_bf16(acc[k].w, h3, l3);
            ushort4 vh = make_ushort4(__bfloat16_as_ushort(h0), __bfloat16_as_ushort(h1),
                                      __bfloat16_as_ushort(h2), __bfloat16_as_ushort(h3));
            ushort4 vl = make_ushort4(__bfloat16_as_ushort(l0), __bfloat16_as_ushort(l1),
                                      __bfloat16_as_ushort(l2), __bfloat16_as_ushort(l3));
            *(ushort4*)(g_Ahi + rowoff + (size_t)k * CIN) = vh;
            *(ushort4*)(g_Alo + rowoff + (size_t)k * CIN) = vl;
        }
    }
}

// ---------------------------------------------------------------------------
// Kernel 2: mma.sync bf16 split GEMM.
//   C[N,128] = Ahi·Bhi^T + Ahi·Blo^T + Alo·Bhi^T  (fp32 register accumulate)
// CTA: 64(M) x 128(N), 8 warps (2 M x 4 N), warp tile 32x32.
// K chunked by 64 bf16 (SW128 128B rows), cp.async double-buffered.
// ---------------------------------------------------------------------------
#define KC      64
#define CHUNKS  (KDIM / KC)    // 30
// stage layout (bytes): Ah 8K | Al 8K | Bh 16K | Bl 16K  = 48K per stage
#define SA_H  0
#define SA_L  8192
#define SB_H  16384
#define SB_L  32768
#define ST_BYTES 49152
#define SMEM_TOTAL (2 * ST_BYTES)   // 96 KB

__global__ void __launch_bounds__(256, 2) kp_mma_gemm_kernel(float* __restrict__ C, int N)
{
    extern __shared__ char smem[];
    uint32_t sbase = smem_u32(smem);
    int tid  = threadIdx.x;
    int wid  = tid >> 5;
    int lane = tid & 31;
    int m0   = blockIdx.x * 64;

    int wm = wid & 1;          // 0..1 : warp row (32 M each)
    int wn = wid >> 1;         // 0..3 : warp col (32 N each)

    // cp.async load map
    int seg = tid & 7;         // 16B segment within 128B row
    int rb  = tid >> 3;        // 0..31

    const __nv_bfloat16* Ah = g_Ahi;
    const __nv_bfloat16* Al = g_Alo;
    const __nv_bfloat16* Bh = g_Bhi;
    const __nv_bfloat16* Bl = g_Blo;

    float acc[2][4][4];
    #pragma unroll
    for (int i = 0; i < 2; i++)
        #pragma unroll
        for (int j = 0; j < 4; j++)
            #pragma unroll
            for (int q = 0; q < 4; q++) acc[i][j][q] = 0.0f;

    // ---- chunk loader ----
    auto load_chunk = [&](int stage, int c) {
        uint32_t sb = sbase + stage * ST_BYTES;
        size_t c0 = (size_t)c * KC + (size_t)seg * 8;   // element offset in K
        #pragma unroll
        for (int g = 0; g < 2; ++g) {                   // A: 64 rows
            int r  = g * 32 + rb;
            int ra = m0 + r; if (ra >= N) ra = N - 1;
            uint32_t off = swz(r, seg);
            cp_async16(sb + SA_H + off, Ah + (size_t)ra * KDIM + c0);
            cp_async16(sb + SA_L + off, Al + (size_t)ra * KDIM + c0);
        }
        #pragma unroll
        for (int g = 0; g < 4; ++g) {                   // B: 128 rows
            int r = g * 32 + rb;
            uint32_t off = swz(r, seg);
            cp_async16(sb + SB_H + off, Bh + (size_t)r * KDIM + c0);
            cp_async16(sb + SB_L + off, Bl + (size_t)r * KDIM + c0);
        }
        cp_async_commit();
    };

    // ldmatrix per-lane row indices
    int a_r15 = lane & 15;         // + wm*32 + mt*16
    int a_kx  = lane >> 4;         // seg += this
    int b_r   = ((lane >> 4) << 3) + (lane & 7);   // + wn*32 + nt2*16
    int b_kx  = (lane >> 3) & 1;

    // Prologue
    load_chunk(0, 0);

    for (int c = 0; c < CHUNKS; ++c) {
        int cur = c & 1;
        if (c + 1 < CHUNKS) load_chunk(cur ^ 1, c + 1);

        if (c + 1 < CHUNKS) cp_async_wait<1>();
        else                cp_async_wait<0>();
        __syncthreads();

        uint32_t sb = sbase + cur * ST_BYTES;

        #pragma unroll
        for (int ks = 0; ks < 4; ++ks) {
            // A fragments (hi & lo): 2 m-tiles
            uint32_t ah[2][4], al[2][4];
            #pragma unroll
            for (int mt = 0; mt < 2; ++mt) {
                int r  = wm * 32 + mt * 16 + a_r15;
                int sg = ks * 2 + a_kx;
                uint32_t off = swz(r, sg);
                ldm_x4(ah[mt][0], ah[mt][1], ah[mt][2], ah[mt][3], sb + SA_H + off);
                ldm_x4(al[mt][0], al[mt][1], al[mt][2], al[mt][3], sb + SA_L + off);
            }
            // B fragments (hi & lo): 4 n-tiles via 2 x4-loads each
            uint32_t bh[4][2], bl[4][2];
            #pragma unroll
            for (int nt2 = 0; nt2 < 2; ++nt2) {
                int r  = wn * 32 + nt2 * 16 + b_r;
                int sg = ks * 2 + b_kx;
                uint32_t off = swz(r, sg);
                uint32_t r0, r1, r2, r3;
                ldm_x4(r0, r1, r2, r3, sb + SB_H + off);
                bh[nt2 * 2 + 0][0] = r0; bh[nt2 * 2 + 0][1] = r1;
                bh[nt2 * 2 + 1][0] = r2; bh[nt2 * 2 + 1][1] = r3;
                ldm_x4(r0, r1, r2, r3, sb + SB_L + off);
                bl[nt2 * 2 + 0][0] = r0; bl[nt2 * 2 + 0][1] = r1;
                bl[nt2 * 2 + 1][0] = r2; bl[nt2 * 2 + 1][1] = r3;
            }
            // 3-product accumulation
            #pragma unroll
            for (int mt = 0; mt < 2; ++mt)
                #pragma unroll
                for (int nt = 0; nt < 4; ++nt) {
                    float* cc = acc[mt][nt];
                    mma_bf16(cc[0], cc[1], cc[2], cc[3],
                             ah[mt][0], ah[mt][1], ah[mt][2], ah[mt][3],
                             bh[nt][0], bh[nt][1]);
                    mma_bf16(cc[0], cc[1], cc[2], cc[3],
                             ah[mt][0], ah[mt][1], ah[mt][2], ah[mt][3],
                             bl[nt][0], bl[nt][1]);
                    mma_bf16(cc[0], cc[1], cc[2], cc[3],
                             al[mt][0], al[mt][1], al[mt][2], al[mt][3],
                             bh[nt][0], bh[nt][1]);
                }
        }
        __syncthreads();
    }

    // Epilogue: direct stores (float2 per mma row)
    int tq = lane >> 2;            // 0..7
    int tr = (lane & 3) * 2;       // 0,2,4,6
    #pragma unroll
    for (int mt = 0; mt < 2; ++mt) {
        #pragma unroll
        for (int nt = 0; nt < 4; ++nt) {
            int gm = m0 + wm * 32 + mt * 16 + tq;
            int gn = wn * 32 + nt * 8 + tr;
            float* cc = acc[mt][nt];
            if (gm < N)     *(float2*)&C[(size_t)gm * COUT + gn]       = make_float2(cc[0], cc[1]);
            if (gm + 8 < N) *(float2*)&C[(size_t)(gm + 8) * COUT + gn] = make_float2(cc[2], cc[3]);
        }
    }
}

// ---------------------------------------------------------------------------
// kernel_launch
// Inputs: q_pts [N,3] f32, s_pts [Ns,3] f32, neighb_inds [N,H] i32,
// x [Ns,CIN] f32, kernel_points [KPTS,3] f32, weights [KPTS,CIN,COUT] f32.
// Output: [N,COUT] f32.
// ---------------------------------------------------------------------------
extern "C" void kernel_launch(void* const* d_in, const int* in_sizes, int n_in,
                              void* d_out, int out_size)
{
    const float* q_pts = (const float*)d_in[0];
    const float* s_pts = (const float*)d_in[1];
    const int*   nb    = (const int*)d_in[2];
    const float* x     = (const float*)d_in[3];
    const float* kp    = (const float*)d_in[4];
    const float* w     = (const float*)d_in[5];
    float*       out   = (float*)d_out;

    int N  = in_sizes[0] / 3;
    int Ns = in_sizes[1] / 3;

    static int smem_set = 0;
    if (!smem_set) {
        cudaFuncSetAttribute(kp_mma_gemm_kernel,
                             cudaFuncAttributeMaxDynamicSharedMemorySize, SMEM_TOTAL);
        smem_set = 1;
    }

    kp_bprep_kernel<<<KDIM, COUT>>>(w);

    int grid1 = (N + 7) / 8;
    kp_weight_kernel<<<grid1, 256>>>(q_pts, s_pts, nb, x, kp, N, Ns);

    int grid2 = (N + 63) / 64;
    kp_mma_gemm_kernel<<<grid2, 256, SMEM_TOTAL>>>(out, N);
}